// round 14
// baseline (speedup 1.0000x reference)
#include <cuda_runtime.h>
#include <cuda_fp16.h>
#include <cstdint>

// Problem constants
constexpr int Bb = 4;
constexpr int Nn = 2048;
constexpr int E  = 1024;
constexpr int H  = 16;
constexpr int HD = 64;
constexpr int M  = Bb * Nn;       // 8192
constexpr int F3 = 3 * E;         // 3072

// Static scratch (half precision operands)
__device__ __half g_xh[(size_t)M * E];
__device__ __half g_wqh[(size_t)F3 * E];    // Q rows pre-scaled by log2e/8
__device__ __half g_wph[(size_t)E * E];
__device__ __half g_qkvh[(size_t)M * F3];   // gemm1 output (half)
__device__ __half g_svh[(size_t)M * E];     // half copy of sv for gemm3

// ---------------------------------------------------------------------------
// helpers
// ---------------------------------------------------------------------------
__device__ __forceinline__ uint32_t smem_u32(const void* p) {
    uint32_t a;
    asm("{ .reg .u64 t; cvta.to.shared.u64 t, %1; cvt.u32.u64 %0, t; }"
        : "=r"(a) : "l"(p));
    return a;
}

__device__ __forceinline__ void cpa16(uint32_t dst, const void* src) {
    asm volatile("cp.async.cg.shared.global [%0], [%1], 16;"
                 :: "r"(dst), "l"(src));
}

// mma.sync m16n8k16 fp16 -> fp32 accum
__device__ __forceinline__ void mmah(float c[4], uint32_t a0, uint32_t a1,
                                     uint32_t a2, uint32_t a3,
                                     uint32_t b0, uint32_t b1) {
    asm volatile(
        "mma.sync.aligned.m16n8k16.row.col.f32.f16.f16.f32 "
        "{%0,%1,%2,%3}, {%4,%5,%6,%7}, {%8,%9}, {%0,%1,%2,%3};"
        : "+f"(c[0]), "+f"(c[1]), "+f"(c[2]), "+f"(c[3])
        : "r"(a0), "r"(a1), "r"(a2), "r"(a3), "r"(b0), "r"(b1));
}

__device__ __forceinline__ void ldmx4(uint32_t r[4], uint32_t addr) {
    asm volatile("ldmatrix.sync.aligned.m8n8.x4.shared.b16 {%0,%1,%2,%3}, [%4];"
                 : "=r"(r[0]), "=r"(r[1]), "=r"(r[2]), "=r"(r[3]) : "r"(addr));
}

__device__ __forceinline__ void ldmx4t(uint32_t r[4], uint32_t addr) {
    asm volatile(
        "ldmatrix.sync.aligned.m8n8.x4.trans.shared.b16 {%0,%1,%2,%3}, [%4];"
        : "=r"(r[0]), "=r"(r[1]), "=r"(r[2]), "=r"(r[3]) : "r"(addr));
}

// packed half2 exp2 (one MUFU op for two values)
__device__ __forceinline__ uint32_t h2exp2(float x, float y) {
    __half2 h = __floats2half2_rn(x, y);
    uint32_t u = *(uint32_t*)&h, r;
    asm("ex2.approx.f16x2 %0, %1;" : "=r"(r) : "r"(u));
    return r;
}

// ---------------------------------------------------------------------------
// fused fp32 -> fp16 convert pass (x | W_qkv | W_proj in one launch)
// ---------------------------------------------------------------------------
constexpr size_t N4_X  = (size_t)M * E / 4;
constexpr size_t N4_WQ = (size_t)F3 * E / 4;
constexpr size_t N4_WP = (size_t)E * E / 4;
constexpr size_t N4_ALL = N4_X + N4_WQ + N4_WP;

__global__ void conv_all(const float* __restrict__ x,
                         const float* __restrict__ wq,
                         const float* __restrict__ wp) {
    size_t i = (size_t)blockIdx.x * blockDim.x + threadIdx.x;
    const float* in;
    __half2* o;
    float sc = 1.0f;
    if (i < N4_X) {
        in = x + 4 * i;
        o  = (__half2*)(g_xh + 4 * i);
    } else if (i < N4_X + N4_WQ) {
        size_t j = i - N4_X;
        in = wq + 4 * j;
        o  = (__half2*)(g_wqh + 4 * j);
        if (j * 4 < (size_t)E * E) sc = 0.125f * 1.4426950408889634f;
    } else {
        size_t j = i - N4_X - N4_WQ;
        if (j >= N4_WP) return;
        in = wp + 4 * j;
        o  = (__half2*)(g_wph + 4 * j);
    }
    float4 v = *(const float4*)in;
    o[0] = __floats2half2_rn(v.x * sc, v.y * sc);
    o[1] = __floats2half2_rn(v.z * sc, v.w * sc);
}

// ---------------------------------------------------------------------------
// FP16 GEMM "NT": C[Md,Nd] = A[Md,Kd] * B[Nd,Kd]^T, half in, fp32 accum.
// CTA tile 128x128, 4 warps (2x2), warp tile 64x64, BK=64 (128B rows, XOR
// swizzle chunk^(row&7)), 3-stage cp.async, 1 sync/k-block, 2 CTAs/SM.
// ---------------------------------------------------------------------------
constexpr int GSTG_B = 32768;                 // A 16KB + B 16KB
constexpr int GEMM_SMEM = 3 * GSTG_B;         // 98304 per CTA

__device__ __forceinline__ void gstage(uint32_t sb, int st,
                                       const __half* __restrict__ A,
                                       const __half* __restrict__ Bm,
                                       int Kd, int kbase, int bm, int bn,
                                       int tid) {
    const uint32_t base = sb + st * GSTG_B;
#pragma unroll
    for (int i = 0; i < 8; i++) {
        int idx = tid + 128 * i;
        int r = idx >> 3, c = idx & 7;
        cpa16(base + r * 128 + ((c ^ (r & 7)) << 4),
              A + (size_t)(bm * 128 + r) * Kd + kbase + c * 8);
    }
#pragma unroll
    for (int i = 0; i < 8; i++) {
        int idx = tid + 128 * i;
        int r = idx >> 3, c = idx & 7;
        cpa16(base + 16384 + r * 128 + ((c ^ (r & 7)) << 4),
              Bm + (size_t)(bn * 128 + r) * Kd + kbase + c * 8);
    }
}

__global__ __launch_bounds__(128, 2)
void gemm_h(const __half* __restrict__ A, const __half* __restrict__ Bm,
            void* __restrict__ Cout, int Nd, int Kd, int halfOut)
{
    extern __shared__ char smc[];
    const uint32_t sb = smem_u32(smc);

    const int tid  = threadIdx.x;
    const int wid  = tid >> 5;
    const int lane = tid & 31;
    const int g    = lane >> 2;
    const int tg   = lane & 3;
    const int wm   = wid & 1;
    const int wn   = wid >> 1;
    const int bm = blockIdx.y, bn = blockIdx.x;

    const int within = lane & 7;
    const int q01 = (lane >> 3) & 1;
    const int q23 = lane >> 4;

    int arow[4], asw[4];
#pragma unroll
    for (int mt = 0; mt < 4; mt++) {
        int r = wm * 64 + mt * 16 + q01 * 8 + within;
        arow[mt] = r * 128;
        asw[mt]  = r & 7;
    }
    int brow[4], bsw[4];
#pragma unroll
    for (int j = 0; j < 4; j++) {
        int r = wn * 64 + j * 16 + q23 * 8 + within;
        brow[j] = r * 128;
        bsw[j]  = r & 7;
    }

    float acc[4][8][4];
#pragma unroll
    for (int i = 0; i < 4; i++)
#pragma unroll
        for (int j = 0; j < 8; j++)
#pragma unroll
            for (int r = 0; r < 4; r++) acc[i][j][r] = 0.0f;

    const int NB = Kd / 64;

    gstage(sb, 0, A, Bm, Kd, 0, bm, bn, tid);
    asm volatile("cp.async.commit_group;" ::: "memory");
    gstage(sb, 1, A, Bm, Kd, 64, bm, bn, tid);
    asm volatile("cp.async.commit_group;" ::: "memory");

    for (int kb = 0; kb < NB; kb++) {
        if (kb == NB - 1)
            asm volatile("cp.async.wait_group 0;" ::: "memory");
        else
            asm volatile("cp.async.wait_group 1;" ::: "memory");
        __syncthreads();

        if (kb + 2 < NB) {
            gstage(sb, (kb + 2) % 3, A, Bm, Kd, (kb + 2) * 64, bm, bn, tid);
            asm volatile("cp.async.commit_group;" ::: "memory");
        }

        const uint32_t Au = sb + (kb % 3) * GSTG_B;
        const uint32_t Bu = Au + 16384;

#pragma unroll
        for (int ks = 0; ks < 4; ks++) {
            uint32_t a[4][4];
#pragma unroll
            for (int mt = 0; mt < 4; mt++)
                ldmx4(a[mt], Au + arow[mt] + (((2 * ks + q23) ^ asw[mt]) << 4));
            uint32_t bb[4][4];
#pragma unroll
            for (int j = 0; j < 4; j++)
                ldmx4(bb[j], Bu + brow[j] + (((2 * ks + q01) ^ bsw[j]) << 4));
#pragma unroll
            for (int nt = 0; nt < 8; nt++) {
                uint32_t b0 = bb[nt >> 1][(nt & 1) * 2];
                uint32_t b1 = bb[nt >> 1][(nt & 1) * 2 + 1];
#pragma unroll
                for (int mt = 0; mt < 4; mt++)
                    mmah(acc[mt][nt], a[mt][0], a[mt][1], a[mt][2], a[mt][3],
                         b0, b1);
            }
        }
    }

    // epilogue
#pragma unroll
    for (int mt = 0; mt < 4; mt++) {
#pragma unroll
        for (int nt = 0; nt < 8; nt++) {
            int row = bm * 128 + wm * 64 + mt * 16 + g;
            int col = bn * 128 + wn * 64 + nt * 8 + 2 * tg;
            if (halfOut) {
                __half* C = (__half*)Cout;
                *(__half2*)&C[(size_t)row * Nd + col] =
                    __floats2half2_rn(acc[mt][nt][0], acc[mt][nt][1]);
                *(__half2*)&C[(size_t)(row + 8) * Nd + col] =
                    __floats2half2_rn(acc[mt][nt][2], acc[mt][nt][3]);
            } else {
                float* C = (float*)Cout;
                *(float2*)&C[(size_t)row * Nd + col] =
                    make_float2(acc[mt][nt][0], acc[mt][nt][1]);
                *(float2*)&C[(size_t)(row + 8) * Nd + col] =
                    make_float2(acc[mt][nt][2], acc[mt][nt][3]);
            }
        }
    }
}

// ---------------------------------------------------------------------------
// FP16 flash attention, register-resident P, fixed-max log2-domain softmax,
// CROSS-TILE pipeline: per iteration compute S(t), then PV(t-1) (independent
// HMMA chains interleaved by the scheduler), then exp(t). 4 smem stages so
// the prefetch (t+2) never touches the V(t-1) stage being read.
// CTA = (b, h, 128 q-rows), 8 warps, 64-kv tiles, 2 CTAs/SM.
// ---------------------------------------------------------------------------
constexpr int KVSTG_B = 16384;               // K 8KB + V 8KB (64 kv rows)
constexpr int ATTN_SMEM = 4 * KVSTG_B;       // 65536
constexpr uint32_t ONE2 = 0x3C003C00u;       // half2(1.0, 1.0)

__device__ __forceinline__ void kvstage(uint32_t sb, int st, int b, int kv0,
                                        int h, int tid) {
    const uint32_t base = sb + st * KVSTG_B;
    const int r  = tid >> 2;                 // 0..63
    const int c0 = (tid & 3) * 2;
    const __half* src = g_qkvh + (size_t)(b * Nn + kv0 + r) * F3 + h * HD;
    const int sw = r & 7;
#pragma unroll
    for (int i = 0; i < 2; i++) {
        int c = c0 + i;
        uint32_t d = base + r * 128 + ((c ^ sw) << 4);
        cpa16(d,        src + E     + c * 8);   // K
        cpa16(d + 8192, src + 2 * E + c * 8);   // V
    }
}

__global__ __launch_bounds__(256, 2)
void attn_h(float* __restrict__ sv)
{
    extern __shared__ char smc[];
    const uint32_t sb = smem_u32(smc);

    const int tid  = threadIdx.x;
    const int wid  = tid >> 5;
    const int lane = tid & 31;
    const int g    = lane >> 2;
    const int tg   = lane & 3;
    const int qrow = wid * 16;

    const int within = lane & 7;
    const int q01 = (lane >> 3) & 1;
    const int q23 = lane >> 4;

    const int q0 = blockIdx.x * 128;
    const int h  = blockIdx.y;
    const int b  = blockIdx.z;

    // ---- prologue: Q into stage-3 region + kv0 (C0); kv1 (C1) ----
    {
        const uint32_t qb = sb + 3 * KVSTG_B;
        const int r  = tid >> 1;             // 0..127
        const int c0 = (tid & 1) * 4;
        const __half* src = g_qkvh + (size_t)(b * Nn + q0 + r) * F3 + h * HD;
        const int sw = r & 7;
#pragma unroll
        for (int i = 0; i < 4; i++) {
            int c = c0 + i;
            cpa16(qb + r * 128 + ((c ^ sw) << 4), src + c * 8);
        }
        kvstage(sb, 0, b, 0, h, tid);
        asm volatile("cp.async.commit_group;" ::: "memory");   // C0: Q + kv0
        kvstage(sb, 1, b, 64, h, tid);
        asm volatile("cp.async.commit_group;" ::: "memory");   // C1: kv1
        asm volatile("cp.async.wait_group 1;" ::: "memory");   // C0 done
        __syncthreads();
    }

    // ---- Q fragments -> registers (from stage-3 region) ----
    uint32_t qa[4][4];
    {
        const uint32_t Qu = sb + 3 * KVSTG_B;
        int r = qrow + q01 * 8 + within;
        int roff = r * 128, rsw = r & 7;
#pragma unroll
        for (int ks = 0; ks < 4; ks++)
            ldmx4(qa[ks], Qu + roff + (((2 * ks + q23) ^ rsw) << 4));
    }
    __syncthreads();   // all warps read Q before tile-3 staging claims stage 3

    // K b-frag rows: row = j*16 + q23*8 + within
    int krow[4], ksw[4];
#pragma unroll
    for (int j = 0; j < 4; j++) {
        int r = j * 16 + q23 * 8 + within;
        krow[j] = r * 128;
        ksw[j]  = r & 7;
    }
    const int vrbase = q01 * 8 + within;

    float o[8][4];
    float rsacc[4] = {0.0f, 0.0f, 0.0f, 0.0f};   // P @ ones (all tiles)
    uint32_t ph0[8], ph1[8];                     // P fragments of tile t-1
#pragma unroll
    for (int nt = 0; nt < 8; nt++)
#pragma unroll
        for (int j = 0; j < 4; j++) o[nt][j] = 0.0f;

    for (int t = 0; t < 32; t++) {
        if (t == 31)
            asm volatile("cp.async.wait_group 0;" ::: "memory");
        else
            asm volatile("cp.async.wait_group 1;" ::: "memory");
        __syncthreads();
        if (t + 2 < 32) {
            kvstage(sb, (t + 2) & 3, b, (t + 2) * 64, h, tid);
            asm volatile("cp.async.commit_group;" ::: "memory");
        }

        const uint32_t Ku = sb + (t & 3) * KVSTG_B;

        // ---- S(t) = Q * K^T (log2-domain scores) ----
        float s[8][4];
#pragma unroll
        for (int nt = 0; nt < 8; nt++)
#pragma unroll
            for (int j = 0; j < 4; j++) s[nt][j] = 0.0f;

#pragma unroll
        for (int ks = 0; ks < 4; ks++) {
#pragma unroll
            for (int j = 0; j < 4; j++) {
                uint32_t bb[4];
                ldmx4(bb, Ku + krow[j] + (((2 * ks + q01) ^ ksw[j]) << 4));
                mmah(s[2 * j],     qa[ks][0], qa[ks][1], qa[ks][2], qa[ks][3],
                     bb[0], bb[1]);
                mmah(s[2 * j + 1], qa[ks][0], qa[ks][1], qa[ks][2], qa[ks][3],
                     bb[2], bb[3]);
            }
        }

        // ---- PV(t-1): O += P * V, rs += P * ones (independent of S(t)) ----
        if (t > 0) {
            const uint32_t Vu = sb + ((t - 1) & 3) * KVSTG_B + 8192;
#pragma unroll
            for (int ks = 0; ks < 4; ks++) {
                uint32_t a0 = ph0[2 * ks],     a1 = ph1[2 * ks];
                uint32_t a2 = ph0[2 * ks + 1], a3 = ph1[2 * ks + 1];
                mmah(rsacc, a0, a1, a2, a3, ONE2, ONE2);
                int vr = ks * 16 + vrbase;
                uint32_t vb_ = Vu + vr * 128;
                int vsw = vr & 7;
#pragma unroll
                for (int j = 0; j < 4; j++) {
                    uint32_t vb[4];
                    ldmx4t(vb, vb_ + (((2 * j + q23) ^ vsw) << 4));
                    mmah(o[2 * j],     a0, a1, a2, a3, vb[0], vb[1]);
                    mmah(o[2 * j + 1], a0, a1, a2, a3, vb[2], vb[3]);
                }
            }
        }

        // ---- exp(t): p = exp2(s) via f16x2 MUFU -> P fragments ----
#pragma unroll
        for (int nt = 0; nt < 8; nt++) {
            ph0[nt] = h2exp2(s[nt][0], s[nt][1]);
            ph1[nt] = h2exp2(s[nt][2], s[nt][3]);
        }
    }

    // ---- peeled PV(31) ----
    {
        const uint32_t Vu = sb + (31 & 3) * KVSTG_B + 8192;
#pragma unroll
        for (int ks = 0; ks < 4; ks++) {
            uint32_t a0 = ph0[2 * ks],     a1 = ph1[2 * ks];
            uint32_t a2 = ph0[2 * ks + 1], a3 = ph1[2 * ks + 1];
            mmah(rsacc, a0, a1, a2, a3, ONE2, ONE2);
            int vr = ks * 16 + vrbase;
            uint32_t vb_ = Vu + vr * 128;
            int vsw = vr & 7;
#pragma unroll
            for (int j = 0; j < 4; j++) {
                uint32_t vb[4];
                ldmx4t(vb, vb_ + (((2 * j + q23) ^ vsw) << 4));
                mmah(o[2 * j],     a0, a1, a2, a3, vb[0], vb[1]);
                mmah(o[2 * j + 1], a0, a1, a2, a3, vb[2], vb[3]);
            }
        }
    }

    // ---- epilogue (row sums complete in rsacc) ----
    float inv0 = 1.0f / rsacc[0], inv1 = 1.0f / rsacc[2];
#pragma unroll
    for (int nt = 0; nt < 8; nt++) {
        int row = q0 + qrow + g;
        int col = h * HD + nt * 8 + 2 * tg;
        size_t off0 = (size_t)(b * Nn + row) * E + col;
        size_t off1 = (size_t)(b * Nn + row + 8) * E + col;
        float v00 = o[nt][0] * inv0, v01 = o[nt][1] * inv0;
        float v10 = o[nt][2] * inv1, v11 = o[nt][3] * inv1;
        *(float2*)&sv[off0] = make_float2(v00, v01);
        *(float2*)&sv[off1] = make_float2(v10, v11);
        *(__half2*)&g_svh[off0] = __floats2half2_rn(v00, v01);
        *(__half2*)&g_svh[off1] = __floats2half2_rn(v10, v11);
    }
}

// ---------------------------------------------------------------------------
extern "C" void kernel_launch(void* const* d_in, const int* in_sizes, int n_in,
                              void* d_out, int out_size)
{
    (void)in_sizes; (void)n_in; (void)out_size;
    const float* x     = (const float*)d_in[0];
    const float* Wqkv  = (const float*)d_in[1];
    const float* Wproj = (const float*)d_in[2];
    float* out = (float*)d_out;
    float* sv  = out + (size_t)M * E;

    __half *xh, *wqh, *wph, *qkvh, *svh;
    cudaGetSymbolAddress((void**)&xh,   g_xh);
    cudaGetSymbolAddress((void**)&wqh,  g_wqh);
    cudaGetSymbolAddress((void**)&wph,  g_wph);
    cudaGetSymbolAddress((void**)&qkvh, g_qkvh);
    cudaGetSymbolAddress((void**)&svh,  g_svh);

    cudaFuncSetAttribute(gemm_h,
                         cudaFuncAttributeMaxDynamicSharedMemorySize, GEMM_SMEM);
    cudaFuncSetAttribute(attn_h,
                         cudaFuncAttributeMaxDynamicSharedMemorySize, ATTN_SMEM);

    // 0) one fused convert pass (log2e/8 folded into Q rows of W_qkv)
    conv_all<<<(int)((N4_ALL + 255) / 256), 256>>>(x, Wqkv, Wproj);

    // 1) qkv = x @ W_qkv^T  (half output)
    gemm_h<<<dim3(F3 / 128, M / 128), 128, GEMM_SMEM>>>(xh, wqh, qkvh, F3, E, 1);

    // 2) sv = attention(q,k,v) -> second output half (+ half copy)
    attn_h<<<dim3(Nn / 128, H, Bb), 256, ATTN_SMEM>>>(sv);

    // 3) out = sv @ W_proj^T  (float output)
    gemm_h<<<dim3(E / 128, M / 128), 128, GEMM_SMEM>>>(svh, wph, out, E, E, 0);
}

// round 15
// speedup vs baseline: 1.0311x; 1.0311x over previous
#include <cuda_runtime.h>
#include <cuda_fp16.h>
#include <cstdint>

// Problem constants
constexpr int Bb = 4;
constexpr int Nn = 2048;
constexpr int E  = 1024;
constexpr int H  = 16;
constexpr int HD = 64;
constexpr int M  = Bb * Nn;       // 8192
constexpr int F3 = 3 * E;         // 3072

// Static scratch (half precision operands)
__device__ __half g_xh[(size_t)M * E];
__device__ __half g_wqh[(size_t)F3 * E];    // Q rows pre-scaled by log2e/8
__device__ __half g_wph[(size_t)E * E];
__device__ __half g_qkvh[(size_t)M * F3];   // gemm1 output (half)
__device__ __half g_svh[(size_t)M * E];     // half copy of sv for gemm3

// ---------------------------------------------------------------------------
// helpers
// ---------------------------------------------------------------------------
__device__ __forceinline__ uint32_t smem_u32(const void* p) {
    uint32_t a;
    asm("{ .reg .u64 t; cvta.to.shared.u64 t, %1; cvt.u32.u64 %0, t; }"
        : "=r"(a) : "l"(p));
    return a;
}

__device__ __forceinline__ void cpa16(uint32_t dst, const void* src) {
    asm volatile("cp.async.cg.shared.global [%0], [%1], 16;"
                 :: "r"(dst), "l"(src));
}

// mma.sync m16n8k16 fp16 -> fp32 accum
__device__ __forceinline__ void mmah(float c[4], uint32_t a0, uint32_t a1,
                                     uint32_t a2, uint32_t a3,
                                     uint32_t b0, uint32_t b1) {
    asm volatile(
        "mma.sync.aligned.m16n8k16.row.col.f32.f16.f16.f32 "
        "{%0,%1,%2,%3}, {%4,%5,%6,%7}, {%8,%9}, {%0,%1,%2,%3};"
        : "+f"(c[0]), "+f"(c[1]), "+f"(c[2]), "+f"(c[3])
        : "r"(a0), "r"(a1), "r"(a2), "r"(a3), "r"(b0), "r"(b1));
}

__device__ __forceinline__ void ldmx4(uint32_t r[4], uint32_t addr) {
    asm volatile("ldmatrix.sync.aligned.m8n8.x4.shared.b16 {%0,%1,%2,%3}, [%4];"
                 : "=r"(r[0]), "=r"(r[1]), "=r"(r[2]), "=r"(r[3]) : "r"(addr));
}

__device__ __forceinline__ void ldmx4t(uint32_t r[4], uint32_t addr) {
    asm volatile(
        "ldmatrix.sync.aligned.m8n8.x4.trans.shared.b16 {%0,%1,%2,%3}, [%4];"
        : "=r"(r[0]), "=r"(r[1]), "=r"(r[2]), "=r"(r[3]) : "r"(addr));
}

// packed half2 exp2 (one MUFU op for two values)
__device__ __forceinline__ uint32_t h2exp2(float x, float y) {
    __half2 h = __floats2half2_rn(x, y);
    uint32_t u = *(uint32_t*)&h, r;
    asm("ex2.approx.f16x2 %0, %1;" : "=r"(r) : "r"(u));
    return r;
}

// ---------------------------------------------------------------------------
// fused fp32 -> fp16 convert pass (x | W_qkv | W_proj in one launch)
// ---------------------------------------------------------------------------
constexpr size_t N4_X  = (size_t)M * E / 4;
constexpr size_t N4_WQ = (size_t)F3 * E / 4;
constexpr size_t N4_WP = (size_t)E * E / 4;
constexpr size_t N4_ALL = N4_X + N4_WQ + N4_WP;

__global__ void conv_all(const float* __restrict__ x,
                         const float* __restrict__ wq,
                         const float* __restrict__ wp) {
    size_t i = (size_t)blockIdx.x * blockDim.x + threadIdx.x;
    const float* in;
    __half2* o;
    float sc = 1.0f;
    if (i < N4_X) {
        in = x + 4 * i;
        o  = (__half2*)(g_xh + 4 * i);
    } else if (i < N4_X + N4_WQ) {
        size_t j = i - N4_X;
        in = wq + 4 * j;
        o  = (__half2*)(g_wqh + 4 * j);
        if (j * 4 < (size_t)E * E) sc = 0.125f * 1.4426950408889634f;
    } else {
        size_t j = i - N4_X - N4_WQ;
        if (j >= N4_WP) return;
        in = wp + 4 * j;
        o  = (__half2*)(g_wph + 4 * j);
    }
    float4 v = *(const float4*)in;
    o[0] = __floats2half2_rn(v.x * sc, v.y * sc);
    o[1] = __floats2half2_rn(v.z * sc, v.w * sc);
}

// ---------------------------------------------------------------------------
// FP16 GEMM "NT": C[Md,Nd] = A[Md,Kd] * B[Nd,Kd]^T, half in, fp32 accum.
// CTA tile 128x128, 4 warps (2x2), warp tile 64x64, BK=64 (128B rows, XOR
// swizzle chunk^(row&7)), 3-stage cp.async, 1 sync/k-block, 2 CTAs/SM.
// ---------------------------------------------------------------------------
constexpr int GSTG_B = 32768;                 // A 16KB + B 16KB
constexpr int GEMM_SMEM = 3 * GSTG_B;         // 98304 per CTA

__device__ __forceinline__ void gstage(uint32_t sb, int st,
                                       const __half* __restrict__ A,
                                       const __half* __restrict__ Bm,
                                       int Kd, int kbase, int bm, int bn,
                                       int tid) {
    const uint32_t base = sb + st * GSTG_B;
#pragma unroll
    for (int i = 0; i < 8; i++) {
        int idx = tid + 128 * i;
        int r = idx >> 3, c = idx & 7;
        cpa16(base + r * 128 + ((c ^ (r & 7)) << 4),
              A + (size_t)(bm * 128 + r) * Kd + kbase + c * 8);
    }
#pragma unroll
    for (int i = 0; i < 8; i++) {
        int idx = tid + 128 * i;
        int r = idx >> 3, c = idx & 7;
        cpa16(base + 16384 + r * 128 + ((c ^ (r & 7)) << 4),
              Bm + (size_t)(bn * 128 + r) * Kd + kbase + c * 8);
    }
}

__global__ __launch_bounds__(128, 2)
void gemm_h(const __half* __restrict__ A, const __half* __restrict__ Bm,
            void* __restrict__ Cout, int Nd, int Kd, int halfOut)
{
    extern __shared__ char smc[];
    const uint32_t sb = smem_u32(smc);

    const int tid  = threadIdx.x;
    const int wid  = tid >> 5;
    const int lane = tid & 31;
    const int g    = lane >> 2;
    const int tg   = lane & 3;
    const int wm   = wid & 1;
    const int wn   = wid >> 1;
    const int bm = blockIdx.y, bn = blockIdx.x;

    const int within = lane & 7;
    const int q01 = (lane >> 3) & 1;
    const int q23 = lane >> 4;

    int arow[4], asw[4];
#pragma unroll
    for (int mt = 0; mt < 4; mt++) {
        int r = wm * 64 + mt * 16 + q01 * 8 + within;
        arow[mt] = r * 128;
        asw[mt]  = r & 7;
    }
    int brow[4], bsw[4];
#pragma unroll
    for (int j = 0; j < 4; j++) {
        int r = wn * 64 + j * 16 + q23 * 8 + within;
        brow[j] = r * 128;
        bsw[j]  = r & 7;
    }

    float acc[4][8][4];
#pragma unroll
    for (int i = 0; i < 4; i++)
#pragma unroll
        for (int j = 0; j < 8; j++)
#pragma unroll
            for (int r = 0; r < 4; r++) acc[i][j][r] = 0.0f;

    const int NB = Kd / 64;

    gstage(sb, 0, A, Bm, Kd, 0, bm, bn, tid);
    asm volatile("cp.async.commit_group;" ::: "memory");
    gstage(sb, 1, A, Bm, Kd, 64, bm, bn, tid);
    asm volatile("cp.async.commit_group;" ::: "memory");

    for (int kb = 0; kb < NB; kb++) {
        if (kb == NB - 1)
            asm volatile("cp.async.wait_group 0;" ::: "memory");
        else
            asm volatile("cp.async.wait_group 1;" ::: "memory");
        __syncthreads();

        if (kb + 2 < NB) {
            gstage(sb, (kb + 2) % 3, A, Bm, Kd, (kb + 2) * 64, bm, bn, tid);
            asm volatile("cp.async.commit_group;" ::: "memory");
        }

        const uint32_t Au = sb + (kb % 3) * GSTG_B;
        const uint32_t Bu = Au + 16384;

#pragma unroll
        for (int ks = 0; ks < 4; ks++) {
            uint32_t a[4][4];
#pragma unroll
            for (int mt = 0; mt < 4; mt++)
                ldmx4(a[mt], Au + arow[mt] + (((2 * ks + q23) ^ asw[mt]) << 4));
            uint32_t bb[4][4];
#pragma unroll
            for (int j = 0; j < 4; j++)
                ldmx4(bb[j], Bu + brow[j] + (((2 * ks + q01) ^ bsw[j]) << 4));
#pragma unroll
            for (int nt = 0; nt < 8; nt++) {
                uint32_t b0 = bb[nt >> 1][(nt & 1) * 2];
                uint32_t b1 = bb[nt >> 1][(nt & 1) * 2 + 1];
#pragma unroll
                for (int mt = 0; mt < 4; mt++)
                    mmah(acc[mt][nt], a[mt][0], a[mt][1], a[mt][2], a[mt][3],
                         b0, b1);
            }
        }
    }

    // epilogue
#pragma unroll
    for (int mt = 0; mt < 4; mt++) {
#pragma unroll
        for (int nt = 0; nt < 8; nt++) {
            int row = bm * 128 + wm * 64 + mt * 16 + g;
            int col = bn * 128 + wn * 64 + nt * 8 + 2 * tg;
            if (halfOut) {
                __half* C = (__half*)Cout;
                *(__half2*)&C[(size_t)row * Nd + col] =
                    __floats2half2_rn(acc[mt][nt][0], acc[mt][nt][1]);
                *(__half2*)&C[(size_t)(row + 8) * Nd + col] =
                    __floats2half2_rn(acc[mt][nt][2], acc[mt][nt][3]);
            } else {
                float* C = (float*)Cout;
                *(float2*)&C[(size_t)row * Nd + col] =
                    make_float2(acc[mt][nt][0], acc[mt][nt][1]);
                *(float2*)&C[(size_t)(row + 8) * Nd + col] =
                    make_float2(acc[mt][nt][2], acc[mt][nt][3]);
            }
        }
    }
}

// ---------------------------------------------------------------------------
// FP16 flash attention, register-resident P, fixed-max softmax in the log2
// domain. exp via ex2.approx.f16x2 (2 values / MUFU op); row sums via an
// extra all-ones MMA accumulated across ALL tiles (no shuffle reduce).
// CTA = (b, h, 128 q-rows), 8 warps, 64-kv tiles, 3-stage cp.async.
// ---------------------------------------------------------------------------
constexpr int KVSTG_B = 16384;               // K 8KB + V 8KB (64 kv rows)
constexpr int ATTN_SMEM = 3 * KVSTG_B;       // 49152
constexpr uint32_t ONE2 = 0x3C003C00u;       // half2(1.0, 1.0)

__device__ __forceinline__ void kvstage(uint32_t sb, int st, int b, int kv0,
                                        int h, int tid) {
    const uint32_t base = sb + st * KVSTG_B;
    const int r  = tid >> 2;                 // 0..63
    const int c0 = (tid & 3) * 2;
    const __half* src = g_qkvh + (size_t)(b * Nn + kv0 + r) * F3 + h * HD;
    const int sw = r & 7;
#pragma unroll
    for (int i = 0; i < 2; i++) {
        int c = c0 + i;
        uint32_t d = base + r * 128 + ((c ^ sw) << 4);
        cpa16(d,        src + E     + c * 8);   // K
        cpa16(d + 8192, src + 2 * E + c * 8);   // V
    }
}

__global__ __launch_bounds__(256, 2)
void attn_h(float* __restrict__ sv)
{
    extern __shared__ char smc[];
    const uint32_t sb = smem_u32(smc);

    const int tid  = threadIdx.x;
    const int wid  = tid >> 5;
    const int lane = tid & 31;
    const int g    = lane >> 2;
    const int tg   = lane & 3;
    const int qrow = wid * 16;

    const int within = lane & 7;
    const int q01 = (lane >> 3) & 1;
    const int q23 = lane >> 4;

    const int q0 = blockIdx.x * 128;
    const int h  = blockIdx.y;
    const int b  = blockIdx.z;

    // ---- prologue: Q into stage-2 region + kv0 (group C0); kv1 (C1) ----
    {
        const uint32_t qb = sb + 2 * KVSTG_B;
        const int r  = tid >> 1;             // 0..127
        const int c0 = (tid & 1) * 4;
        const __half* src = g_qkvh + (size_t)(b * Nn + q0 + r) * F3 + h * HD;
        const int sw = r & 7;
#pragma unroll
        for (int i = 0; i < 4; i++) {
            int c = c0 + i;
            cpa16(qb + r * 128 + ((c ^ sw) << 4), src + c * 8);
        }
        kvstage(sb, 0, b, 0, h, tid);
        asm volatile("cp.async.commit_group;" ::: "memory");   // C0: Q + kv0
        kvstage(sb, 1, b, 64, h, tid);
        asm volatile("cp.async.commit_group;" ::: "memory");   // C1: kv1
        asm volatile("cp.async.wait_group 1;" ::: "memory");   // C0 done
        __syncthreads();
    }

    // ---- Q fragments -> registers (from stage-2 region) ----
    uint32_t qa[4][4];
    {
        const uint32_t Qu = sb + 2 * KVSTG_B;
        int r = qrow + q01 * 8 + within;
        int roff = r * 128, rsw = r & 7;
#pragma unroll
        for (int ks = 0; ks < 4; ks++)
            ldmx4(qa[ks], Qu + roff + (((2 * ks + q23) ^ rsw) << 4));
    }
    __syncthreads();   // all warps read Q before kv2 claims stage 2

    // K b-frag rows: row = j*16 + q23*8 + within
    int krow[4], ksw[4];
#pragma unroll
    for (int j = 0; j < 4; j++) {
        int r = j * 16 + q23 * 8 + within;
        krow[j] = r * 128;
        ksw[j]  = r & 7;
    }
    const int vrbase = q01 * 8 + within;

    float o[8][4];
    float rsacc[4] = {0.0f, 0.0f, 0.0f, 0.0f};   // P @ ones (all tiles)
#pragma unroll
    for (int nt = 0; nt < 8; nt++)
#pragma unroll
        for (int j = 0; j < 4; j++) o[nt][j] = 0.0f;

    for (int t = 0; t < 32; t++) {
        if (t > 0) {
            if (t + 1 < 32)
                asm volatile("cp.async.wait_group 1;" ::: "memory");
            else
                asm volatile("cp.async.wait_group 0;" ::: "memory");
            __syncthreads();
        }
        if (t + 2 < 32) {
            kvstage(sb, (t + 2) % 3, b, (t + 2) * 64, h, tid);
            asm volatile("cp.async.commit_group;" ::: "memory");
        }

        const uint32_t Ku = sb + (t % 3) * KVSTG_B;
        const uint32_t Vu = Ku + 8192;

        // ---- S = Q * K^T (log2-domain scores) ----
        float s[8][4];
#pragma unroll
        for (int nt = 0; nt < 8; nt++)
#pragma unroll
            for (int j = 0; j < 4; j++) s[nt][j] = 0.0f;

#pragma unroll
        for (int ks = 0; ks < 4; ks++) {
#pragma unroll
            for (int j = 0; j < 4; j++) {
                uint32_t bb[4];
                ldmx4(bb, Ku + krow[j] + (((2 * ks + q01) ^ ksw[j]) << 4));
                mmah(s[2 * j],     qa[ks][0], qa[ks][1], qa[ks][2], qa[ks][3],
                     bb[0], bb[1]);
                mmah(s[2 * j + 1], qa[ks][0], qa[ks][1], qa[ks][2], qa[ks][3],
                     bb[2], bb[3]);
            }
        }

        // ---- p = exp2(s) via f16x2 MUFU; pack P fragments directly ----
        uint32_t ph0[8], ph1[8];
#pragma unroll
        for (int nt = 0; nt < 8; nt++) {
            ph0[nt] = h2exp2(s[nt][0], s[nt][1]);
            ph1[nt] = h2exp2(s[nt][2], s[nt][3]);
        }

        // ---- O += P * V; rs += P * ones (same fp16 P -> consistent) ----
#pragma unroll
        for (int ks = 0; ks < 4; ks++) {
            uint32_t a0 = ph0[2 * ks],     a1 = ph1[2 * ks];
            uint32_t a2 = ph0[2 * ks + 1], a3 = ph1[2 * ks + 1];
            mmah(rsacc, a0, a1, a2, a3, ONE2, ONE2);
            int vr = ks * 16 + vrbase;
            uint32_t vb_ = Vu + vr * 128;
            int vsw = vr & 7;
#pragma unroll
            for (int j = 0; j < 4; j++) {
                uint32_t vb[4];
                ldmx4t(vb, vb_ + (((2 * j + q23) ^ vsw) << 4));
                mmah(o[2 * j],     a0, a1, a2, a3, vb[0], vb[1]);
                mmah(o[2 * j + 1], a0, a1, a2, a3, vb[2], vb[3]);
            }
        }
    }

    // ---- epilogue (row sums already complete in rsacc) ----
    float inv0 = 1.0f / rsacc[0], inv1 = 1.0f / rsacc[2];
#pragma unroll
    for (int nt = 0; nt < 8; nt++) {
        int row = q0 + qrow + g;
        int col = h * HD + nt * 8 + 2 * tg;
        size_t off0 = (size_t)(b * Nn + row) * E + col;
        size_t off1 = (size_t)(b * Nn + row + 8) * E + col;
        float v00 = o[nt][0] * inv0, v01 = o[nt][1] * inv0;
        float v10 = o[nt][2] * inv1, v11 = o[nt][3] * inv1;
        *(float2*)&sv[off0] = make_float2(v00, v01);
        *(float2*)&sv[off1] = make_float2(v10, v11);
        *(__half2*)&g_svh[off0] = __floats2half2_rn(v00, v01);
        *(__half2*)&g_svh[off1] = __floats2half2_rn(v10, v11);
    }
}

// ---------------------------------------------------------------------------
extern "C" void kernel_launch(void* const* d_in, const int* in_sizes, int n_in,
                              void* d_out, int out_size)
{
    (void)in_sizes; (void)n_in; (void)out_size;
    const float* x     = (const float*)d_in[0];
    const float* Wqkv  = (const float*)d_in[1];
    const float* Wproj = (const float*)d_in[2];
    float* out = (float*)d_out;
    float* sv  = out + (size_t)M * E;

    __half *xh, *wqh, *wph, *qkvh, *svh;
    cudaGetSymbolAddress((void**)&xh,   g_xh);
    cudaGetSymbolAddress((void**)&wqh,  g_wqh);
    cudaGetSymbolAddress((void**)&wph,  g_wph);
    cudaGetSymbolAddress((void**)&qkvh, g_qkvh);
    cudaGetSymbolAddress((void**)&svh,  g_svh);

    cudaFuncSetAttribute(gemm_h,
                         cudaFuncAttributeMaxDynamicSharedMemorySize, GEMM_SMEM);
    cudaFuncSetAttribute(attn_h,
                         cudaFuncAttributeMaxDynamicSharedMemorySize, ATTN_SMEM);

    // 0) one fused convert pass (log2e/8 folded into Q rows of W_qkv)
    conv_all<<<(int)((N4_ALL + 255) / 256), 256>>>(x, Wqkv, Wproj);

    // 1) qkv = x @ W_qkv^T  (half output)
    gemm_h<<<dim3(F3 / 128, M / 128), 128, GEMM_SMEM>>>(xh, wqh, qkvh, F3, E, 1);

    // 2) sv = attention(q,k,v) -> second output half (+ half copy)
    attn_h<<<dim3(Nn / 128, H, Bb), 256, ATTN_SMEM>>>(sv);

    // 3) out = sv @ W_proj^T  (float output)
    gemm_h<<<dim3(E / 128, M / 128), 128, GEMM_SMEM>>>(svh, wph, out, E, E, 0);
}